// round 10
// baseline (speedup 1.0000x reference)
#include <cuda_runtime.h>
#include <cuda_bf16.h>
#include <math.h>

#define N_NODES_MAX 100000
#define N_EDGES_MAX 3200000
#define D 64
#define NL 3
#define SCAN_B 256
#define MAX_NB ((N_NODES_MAX + SCAN_B - 1) / SCAN_B + 1)

// ---- device scratch (no allocation allowed). 256B-aligned for vector loads. ----
// Edge record: .x = src id (bit-cast int), .y/.z/.w = softplus weight for layer 0/1/2
__device__ __align__(256) float4 g_edges[N_EDGES_MAX];
__device__ __align__(256) int   g_deg[N_NODES_MAX];
__device__ __align__(256) int   g_offs[N_NODES_MAX + 1];
__device__ __align__(256) int   g_cur[N_NODES_MAX];
__device__ __align__(256) int   g_bsum[MAX_NB];
__device__ __align__(256) int   g_boff[MAX_NB];
__device__ __align__(256) float g_hA[(size_t)N_NODES_MAX * D];
__device__ __align__(256) float g_hB[(size_t)N_NODES_MAX * D];
__device__ __align__(256) __nv_bfloat16 g_xb [(size_t)N_NODES_MAX * D];
__device__ __align__(256) __nv_bfloat16 g_hbA[(size_t)N_NODES_MAX * D];
__device__ __align__(256) __nv_bfloat16 g_hbB[(size_t)N_NODES_MAX * D];
__device__ int g_is64;

// ---------------------------------------------------------------------------
__global__ void detect_kernel(const int* __restrict__ w32)
{
    __shared__ int any;
    if (threadIdx.x == 0) any = 0;
    __syncthreads();
    int acc = 0;
    for (int i = threadIdx.x * 2 + 1; i < 4096; i += blockDim.x * 2)
        acc |= w32[i];
    if (acc) atomicOr(&any, 1);
    __syncthreads();
    if (threadIdx.x == 0) g_is64 = (any == 0) ? 1 : 0;
}

__global__ void zero_deg_kernel(int n)
{
    int i = blockIdx.x * blockDim.x + threadIdx.x;
    if (i < n) g_deg[i] = 0;
}

__global__ void hist_kernel(const void* __restrict__ eidx_raw, int E)
{
    int e = blockIdx.x * blockDim.x + threadIdx.x;
    if (e >= E) return;
    int d;
    if (g_is64) d = (int)((const long long*)eidx_raw)[(size_t)E + e];
    else        d = ((const int*)eidx_raw)[(size_t)E + e];
    atomicAdd(&g_deg[d], 1);
}

__global__ void scan_phase1(int N)
{
    __shared__ int sh[SCAN_B];
    const int tid = threadIdx.x;
    const int i = blockIdx.x * SCAN_B + tid;
    int v = (i < N) ? g_deg[i] : 0;
    sh[tid] = v;
    __syncthreads();
    for (int off = 1; off < SCAN_B; off <<= 1) {
        int a = sh[tid];
        int b = (tid >= off) ? sh[tid - off] : 0;
        __syncthreads();
        sh[tid] = a + b;
        __syncthreads();
    }
    if (i < N) g_offs[i] = sh[tid] - v;
    if (tid == SCAN_B - 1) g_bsum[blockIdx.x] = sh[SCAN_B - 1];
}

__global__ void scan_phase2(int NB)
{
    __shared__ int sh[1024];
    const int tid = threadIdx.x;
    int v = (tid < NB) ? g_bsum[tid] : 0;
    sh[tid] = v;
    __syncthreads();
    for (int off = 1; off < 1024; off <<= 1) {
        int a = sh[tid];
        int b = (tid >= off) ? sh[tid - off] : 0;
        __syncthreads();
        sh[tid] = a + b;
        __syncthreads();
    }
    if (tid < NB) g_boff[tid] = sh[tid] - v;
}

__global__ void scan_phase3(int N)
{
    const int i = blockIdx.x * SCAN_B + threadIdx.x;
    if (i < N) {
        int o = g_offs[i] + g_boff[blockIdx.x];
        g_offs[i] = o;
        g_cur[i]  = o;
        if (i == N - 1) g_offs[N] = o + g_deg[i];
    }
}

__global__ void place_kernel(const void* __restrict__ eidx_raw,
                             const float* __restrict__ eattr,
                             const float* __restrict__ emlp_w,
                             const float* __restrict__ emlp_b,
                             int E)
{
    int e = blockIdx.x * blockDim.x + threadIdx.x;
    if (e >= E) return;

    int s, d;
    if (g_is64) {
        const long long* p = (const long long*)eidx_raw;
        s = (int)p[e];
        d = (int)p[(size_t)E + e];
    } else {
        const int* p = (const int*)eidx_raw;
        s = p[e];
        d = p[(size_t)E + e];
    }

    const float4 a0 = *(const float4*)(eattr + (size_t)e * 8);
    const float4 a1 = *(const float4*)(eattr + (size_t)e * 8 + 4);

    float sp[NL];
#pragma unroll
    for (int l = 0; l < NL; l++) {
        const float* wp = emlp_w + l * 8;
        float z = emlp_b[l];
        z = fmaf(a0.x, wp[0], z);
        z = fmaf(a0.y, wp[1], z);
        z = fmaf(a0.z, wp[2], z);
        z = fmaf(a0.w, wp[3], z);
        z = fmaf(a1.x, wp[4], z);
        z = fmaf(a1.y, wp[5], z);
        z = fmaf(a1.z, wp[6], z);
        z = fmaf(a1.w, wp[7], z);
        sp[l] = fmaxf(z, 0.f) + log1pf(expf(-fabsf(z)));
    }

    int pos = atomicAdd(&g_cur[d], 1);
    g_edges[pos] = make_float4(__int_as_float(s), sp[0], sp[1], sp[2]);
}

// ---------------------------------------------------------------------------
__global__ void f2bf_kernel(const float* __restrict__ in,
                            __nv_bfloat16* __restrict__ out, int n)
{
    int idx = (blockIdx.x * blockDim.x + threadIdx.x) * 4;
    if (idx < n) {
        float4 v = *(const float4*)(in + idx);
        *(__nv_bfloat162*)(out + idx)     = __floats2bfloat162_rn(v.x, v.y);
        *(__nv_bfloat162*)(out + idx + 2) = __floats2bfloat162_rn(v.z, v.w);
    }
}

// ---------------------------------------------------------------------------
__device__ __forceinline__ void cvt_fma8(float* acc, uint4 u, float w)
{
    float2 p;
    p = __bfloat1622float2(*reinterpret_cast<__nv_bfloat162*>(&u.x));
    acc[0] = fmaf(w, p.x, acc[0]); acc[1] = fmaf(w, p.y, acc[1]);
    p = __bfloat1622float2(*reinterpret_cast<__nv_bfloat162*>(&u.y));
    acc[2] = fmaf(w, p.x, acc[2]); acc[3] = fmaf(w, p.y, acc[3]);
    p = __bfloat1622float2(*reinterpret_cast<__nv_bfloat162*>(&u.z));
    acc[4] = fmaf(w, p.x, acc[4]); acc[5] = fmaf(w, p.y, acc[5]);
    p = __bfloat1622float2(*reinterpret_cast<__nv_bfloat162*>(&u.w));
    acc[6] = fmaf(w, p.x, acc[6]); acc[7] = fmaf(w, p.y, acc[7]);
}

// ---- packed f32x2 helpers (sm_103a FFMA2; ptxas never emits from C++) ----
__device__ __forceinline__ unsigned long long pk2(float x, float y)
{
    unsigned long long u;
    asm("mov.b64 %0, {%1, %2};" : "=l"(u) : "f"(x), "f"(y));
    return u;
}
__device__ __forceinline__ void ffma2(unsigned long long& d,
                                      unsigned long long a,
                                      unsigned long long b)
{
    asm("fma.rn.f32x2 %0, %1, %2, %0;" : "+l"(d) : "l"(a), "l"(b));
}
__device__ __forceinline__ float2 upk2(unsigned long long u)
{
    float2 f;
    asm("mov.b64 {%0, %1}, %2;" : "=f"(f.x), "=f"(f.y) : "l"(u));
    return f;
}

// ---------------------------------------------------------------------------
// Fused per-layer kernel. Warp per node r. Gather: 16 edges/warp-pass (MLP=4).
// Epilogue GEMM: packed f32x2, all operands from smem, zero shuffles.
//   sWp[k2][j] = (W[j][2k2], W[j][2k2+1])  — lane-contiguous float2.
//   a-pairs broadcast from per-warp smem row.
// ---------------------------------------------------------------------------
template <int L, bool FUSE_FC>
__global__ void __launch_bounds__(256)
layer_kernel(const float* __restrict__ hin,
             const __nv_bfloat16* __restrict__ hin_b,
             float* __restrict__ hout,
             __nv_bfloat16* __restrict__ hout_b,   // may be null
             const float* __restrict__ W,
             const float* __restrict__ bias,
             const float* __restrict__ gamma,
             const float* __restrict__ beta,
             const float* __restrict__ fcW,
             const float* __restrict__ fcb,
             int N)
{
    __shared__ float2 sWp[D / 2][D];                         // 16KB packed weights
    __shared__ float2 sFp[FUSE_FC ? D / 2 : 1][FUSE_FC ? D : 1];
    __shared__ float sb[D], sg[D], sbt[D], sfb[D];
    __shared__ float2 sAv[8][D / 2];                         // per-warp activation row

    for (int i = threadIdx.x; i < D * D / 2; i += blockDim.x) {
        int k2 = i >> 6;          // 0..31
        int j  = i & 63;          // 0..63
        sWp[k2][j] = make_float2(W[j * D + 2 * k2], W[j * D + 2 * k2 + 1]);
        if (FUSE_FC)
            sFp[k2][j] = make_float2(fcW[j * D + 2 * k2], fcW[j * D + 2 * k2 + 1]);
    }
    if (threadIdx.x < D) {
        sb[threadIdx.x]  = bias[threadIdx.x];
        sg[threadIdx.x]  = gamma[threadIdx.x];
        sbt[threadIdx.x] = beta[threadIdx.x];
        if (FUSE_FC) sfb[threadIdx.x] = fcb[threadIdx.x];
    }
    __syncthreads();

    const int warp = threadIdx.x >> 5;
    const int lane = threadIdx.x & 31;
    const int f8      = lane & 7;    // which 16B (8-bf16) chunk of the 128B row
    const int quarter = lane >> 3;   // which of 4 concurrent edges
    const int warps_per_grid = (blockDim.x >> 5) * gridDim.x;
    float* sA = (float*)sAv[warp];   // scalar view of this warp's row

    for (int r = blockIdx.x * (blockDim.x >> 5) + warp; r < N; r += warps_per_grid) {
        const int start = __ldg(g_offs + r);
        const int end   = __ldg(g_offs + r + 1);

        float acc [8] = {0.f, 0.f, 0.f, 0.f, 0.f, 0.f, 0.f, 0.f};
        float acc2[8] = {0.f, 0.f, 0.f, 0.f, 0.f, 0.f, 0.f, 0.f};
        float cw = 0.f, cw2 = 0.f;

        int i = start + quarter;
        for (; i + 12 < end; i += 16) {
            float4 r0 = __ldg(g_edges + i);
            float4 r1 = __ldg(g_edges + i + 4);
            float4 r2 = __ldg(g_edges + i + 8);
            float4 r3 = __ldg(g_edges + i + 12);
            uint4 u0 = __ldg((const uint4*)(hin_b + (size_t)__float_as_int(r0.x) * D) + f8);
            uint4 u1 = __ldg((const uint4*)(hin_b + (size_t)__float_as_int(r1.x) * D) + f8);
            uint4 u2 = __ldg((const uint4*)(hin_b + (size_t)__float_as_int(r2.x) * D) + f8);
            uint4 u3 = __ldg((const uint4*)(hin_b + (size_t)__float_as_int(r3.x) * D) + f8);
            float w0 = (L == 0) ? r0.y : (L == 1) ? r0.z : r0.w;
            float w1 = (L == 0) ? r1.y : (L == 1) ? r1.z : r1.w;
            float w2 = (L == 0) ? r2.y : (L == 1) ? r2.z : r2.w;
            float w3 = (L == 0) ? r3.y : (L == 1) ? r3.z : r3.w;
            cvt_fma8(acc,  u0, w0); cw  += w0;
            cvt_fma8(acc2, u1, w1); cw2 += w1;
            cvt_fma8(acc,  u2, w2); cw  += w2;
            cvt_fma8(acc2, u3, w3); cw2 += w3;
        }
        for (; i < end; i += 4) {
            float4 re = __ldg(g_edges + i);
            float we = (L == 0) ? re.y : (L == 1) ? re.z : re.w;
            uint4 u = __ldg((const uint4*)(hin_b + (size_t)__float_as_int(re.x) * D) + f8);
            cvt_fma8(acc, u, we); cw += we;
        }
#pragma unroll
        for (int j = 0; j < 8; j++) acc[j] += acc2[j];
        cw += cw2;

        // reduce over the 4 quarters (lane bits 3,4)
#pragma unroll
        for (int j = 0; j < 8; j++) {
            acc[j] += __shfl_xor_sync(0xffffffffu, acc[j], 8);
            acc[j] += __shfl_xor_sync(0xffffffffu, acc[j], 16);
        }
        // c = sum w; each edge's w counted by its 8 lanes -> exact /8
#pragma unroll
        for (int o = 16; o > 0; o >>= 1)
            cw += __shfl_xor_sync(0xffffffffu, cw, o);
        cw *= (1.f / 8.f);

        if (lane < 8) {
#pragma unroll
            for (int j = 0; j < 8; j++)
                sA[f8 * 8 + j] = acc[j];
        }
        __syncwarp();

        float hi0 = hin[(size_t)r * D + lane];
        float hi1 = hin[(size_t)r * D + lane + 32];

        // complete the message sum in smem: a = agg - cw*h[r]
        float a0 = sA[lane]      - cw * hi0;
        float a1 = sA[lane + 32] - cw * hi1;
        __syncwarp();
        sA[lane]      = a0;
        sA[lane + 32] = a1;
        __syncwarp();

        // packed GEMM: out[j] = sum_k a[k] * W[j][k]
        unsigned long long p0 = 0ull, p1 = 0ull;
#pragma unroll
        for (int k2 = 0; k2 < D / 2; k2++) {
            float2 ap = sAv[warp][k2];                 // broadcast LDS.64
            unsigned long long a2 = pk2(ap.x, ap.y);
            float2 w0 = sWp[k2][lane];
            float2 w1 = sWp[k2][lane + 32];
            ffma2(p0, a2, pk2(w0.x, w0.y));
            ffma2(p1, a2, pk2(w1.x, w1.y));
        }
        float2 q0 = upk2(p0), q1 = upk2(p1);
        float h0 = fmaxf(q0.x + q0.y + sb[lane], 0.f);
        float h1 = fmaxf(q1.x + q1.y + sb[lane + 32], 0.f);

        float s2 = h0 + h1;
        float sq = h0 * h0 + h1 * h1;
#pragma unroll
        for (int o = 16; o > 0; o >>= 1) {
            s2 += __shfl_xor_sync(0xffffffffu, s2, o);
            sq += __shfl_xor_sync(0xffffffffu, sq, o);
        }
        float mu  = s2 * (1.f / D);
        float var = sq * (1.f / D) - mu * mu;
        float inv = rsqrtf(var + 1e-5f);

        float o0 = (h0 - mu) * inv * sg[lane]      + sbt[lane]      + hi0;
        float o1 = (h1 - mu) * inv * sg[lane + 32] + sbt[lane + 32] + hi1;

        if (FUSE_FC) {
            __syncwarp();
            sA[lane]      = o0;
            sA[lane + 32] = o1;
            __syncwarp();
            unsigned long long f0 = 0ull, f1 = 0ull;
#pragma unroll
            for (int k2 = 0; k2 < D / 2; k2++) {
                float2 ap = sAv[warp][k2];
                unsigned long long a2 = pk2(ap.x, ap.y);
                float2 w0 = sFp[k2][lane];
                float2 w1 = sFp[k2][lane + 32];
                ffma2(f0, a2, pk2(w0.x, w0.y));
                ffma2(f1, a2, pk2(w1.x, w1.y));
            }
            float2 g0 = upk2(f0), g1 = upk2(f1);
            hout[(size_t)r * D + lane]      = g0.x + g0.y + sfb[lane];
            hout[(size_t)r * D + lane + 32] = g1.x + g1.y + sfb[lane + 32];
        } else {
            hout[(size_t)r * D + lane]      = o0;
            hout[(size_t)r * D + lane + 32] = o1;
            hout_b[(size_t)r * D + lane]      = __float2bfloat16(o0);
            hout_b[(size_t)r * D + lane + 32] = __float2bfloat16(o1);
        }
        __syncwarp();
    }
}

// ---------------------------------------------------------------------------
extern "C" void kernel_launch(void* const* d_in, const int* in_sizes, int n_in,
                              void* d_out, int out_size)
{
    const float* x      = (const float*)d_in[0];
    const void*  eidx   = d_in[1];
    const float* eattr  = (const float*)d_in[2];
    const float* lin_w  = (const float*)d_in[3];
    const float* lin_b  = (const float*)d_in[4];
    const float* emlp_w = (const float*)d_in[5];
    const float* emlp_b = (const float*)d_in[6];
    const float* gamma  = (const float*)d_in[7];
    const float* beta   = (const float*)d_in[8];
    const float* fc_w   = (const float*)d_in[9];
    const float* fc_b   = (const float*)d_in[10];
    float*       out    = (float*)d_out;

    const int E = in_sizes[1] / 2;
    const int N = in_sizes[0] / D;

    float *hA, *hB;
    __nv_bfloat16 *xb, *hbA, *hbB;
    cudaGetSymbolAddress((void**)&hA,  g_hA);
    cudaGetSymbolAddress((void**)&hB,  g_hB);
    cudaGetSymbolAddress((void**)&xb,  g_xb);
    cudaGetSymbolAddress((void**)&hbA, g_hbA);
    cudaGetSymbolAddress((void**)&hbB, g_hbB);

    // --- CSR build + edge weights + bf16 shadow of x ---
    const int NB = (N + SCAN_B - 1) / SCAN_B;
    detect_kernel<<<1, 256>>>((const int*)eidx);
    zero_deg_kernel<<<(N + 255) / 256, 256>>>(N);
    hist_kernel<<<(E + 255) / 256, 256>>>(eidx, E);
    scan_phase1<<<NB, SCAN_B>>>(N);
    scan_phase2<<<1, 1024>>>(NB);
    scan_phase3<<<NB, SCAN_B>>>(N);
    place_kernel<<<(E + 255) / 256, 256>>>(eidx, eattr, emlp_w, emlp_b, E);
    f2bf_kernel<<<(N * D / 4 + 255) / 256, 256>>>(x, xb, N * D);

    // --- layers (fused gather + packed-GEMM + LN + residual) ---
    const int blocks = 1480, threads = 256;

    layer_kernel<0, false><<<blocks, threads>>>(x,  xb,  hA, hbA,
                                                lin_w, lin_b, gamma, beta,
                                                nullptr, nullptr, N);
    layer_kernel<1, false><<<blocks, threads>>>(hA, hbA, hB, hbB,
                                                lin_w + (size_t)D * D, lin_b + D,
                                                gamma + D, beta + D,
                                                nullptr, nullptr, N);
    layer_kernel<2, true><<<blocks, threads>>>(hB, hbB, out, nullptr,
                                               lin_w + (size_t)2 * D * D, lin_b + 2 * D,
                                               gamma + 2 * D, beta + 2 * D,
                                               fc_w, fc_b, N);
}